// round 13
// baseline (speedup 1.0000x reference)
#include <cuda_runtime.h>
#include <cuda_bf16.h>
#include <cstdint>

#define N_NODES 100000
#define N_EDGES 1600000
#define TM 128
#define NBLK ((N_NODES + TM - 1) / TM)
#define THREADS 512
#define NPERS 148     // persistent CTAs (~1 per SM)
#define LDK 136       // padded K stride (272B rows -> conflict-free ldmatrix)
#define WBLK 64       // weight-image blocks inside prep_scatter

// ---- SMEM byte offsets (persistent layout: A + B1 + B2 resident together) ----
#define OFF_B1HI 0            // 34816 each  [128][136] bf16
#define OFF_B1LO 34816
#define OFF_B2HI 69632
#define OFF_B2LO 104448
#define OFF_AHI  139264
#define OFF_ALO  174080
#define OFF_MEA  208896       // [128][4] fp32
#define OFF_W1C  210944       // [3][128] fp32
#define OFF_B1   212480       // [128] fp32
#define OFF_B2   212992       // [128] fp32
#define OFF_ZB   213504       // [4] uint32 zero-degree ballots (+pad to 32)
#define OFF_FIX  213536       // [4][128] fp32 per-group fixup scratch
#define SMEM_TOTAL 215584

// ---- global scratch ----
// g_agg invariant: all-zero at launch start. First launch: static zero-init.
// Afterwards fused_kernel consumes-and-clears every entry it reads, so each
// complete execution (and each graph replay) restores the invariant.
__device__ float4 g_agg[N_NODES];                      // sum_ea0..2, count
__device__ __align__(16) __nv_bfloat16 g_B1hi[128 * LDK];  // [n][k] = Wsum[k][n]
__device__ __align__(16) __nv_bfloat16 g_B1lo[128 * LDK];
__device__ __align__(16) __nv_bfloat16 g_B2hi[128 * LDK];  // [n][k] = W2[k][n]
__device__ __align__(16) __nv_bfloat16 g_B2lo[128 * LDK];

__device__ __forceinline__ uint32_t pack_bf(float a, float b) {
    __nv_bfloat162 t = __floats2bfloat162_rn(a, b);
    return *(uint32_t*)&t;
}
__device__ __forceinline__ float bf_resid(float v) {
    return v - __bfloat162float(__float2bfloat16_rn(v));
}
__device__ __forceinline__ void mma_bf16(float* c, const uint32_t* a, const uint32_t* b) {
    asm volatile(
        "mma.sync.aligned.m16n8k16.row.col.f32.bf16.bf16.f32 "
        "{%0,%1,%2,%3}, {%4,%5,%6,%7}, {%8,%9}, {%0,%1,%2,%3};"
        : "+f"(c[0]), "+f"(c[1]), "+f"(c[2]), "+f"(c[3])
        : "r"(a[0]), "r"(a[1]), "r"(a[2]), "r"(a[3]), "r"(b[0]), "r"(b[1]));
}
__device__ __forceinline__ void red_v4(float4* p, float a, float b, float c, float d) {
    asm volatile("red.global.add.v4.f32 [%0], {%1, %2, %3, %4};"
                 :: "l"(p), "f"(a), "f"(b), "f"(c), "f"(d) : "memory");
}
__device__ __forceinline__ void bar_grp(int id) {
    asm volatile("bar.sync %0, %1;" :: "r"(id), "r"(128) : "memory");
}
__device__ __forceinline__ uint32_t smem_u32(const void* p) {
    uint32_t a;
    asm("{ .reg .u64 t; cvta.to.shared.u64 t, %1; cvt.u32.u64 %0, t; }" : "=r"(a) : "l"(p));
    return a;
}
#define LDSM4(r, addr)                                                           \
    asm volatile("ldmatrix.sync.aligned.m8n8.x4.shared.b16 {%0,%1,%2,%3}, [%4];" \
        : "=r"((r)[0]), "=r"((r)[1]), "=r"((r)[2]), "=r"((r)[3]) : "r"(addr))

// ---------------------------------------------------------------------------
// prep_scatter: blocks [0,WBLK) build weight images; the rest scatter edges
// ---------------------------------------------------------------------------
__global__ void prep_scatter_kernel(const int* __restrict__ ei32,
                                    const float* __restrict__ ea,
                                    const float* __restrict__ W1,
                                    const float* __restrict__ W2) {
    int b = blockIdx.x;
    if (b < WBLK) {
        int tid = b * blockDim.x + threadIdx.x;
        int stride = WBLK * blockDim.x;
        for (int i = tid; i < 128 * 128; i += stride) {
            int n = i >> 7, k = i & 127;
            float v = W1[k * 128 + n] + W1[(128 + k) * 128 + n];   // Wsum^T
            __nv_bfloat16 h = __float2bfloat16_rn(v);
            g_B1hi[n * LDK + k] = h;
            g_B1lo[n * LDK + k] = __float2bfloat16_rn(v - __bfloat162float(h));
            float w = W2[k * 128 + n];                              // W2^T
            __nv_bfloat16 h2 = __float2bfloat16_rn(w);
            g_B2hi[n * LDK + k] = h2;
            g_B2lo[n * LDK + k] = __float2bfloat16_rn(w - __bfloat162float(h2));
        }
        for (int i = tid; i < 128 * (LDK - 128); i += stride) {
            int n = i / (LDK - 128), k = 128 + i % (LDK - 128);
            g_B1hi[n * LDK + k] = __float2bfloat16_rn(0.f);
            g_B1lo[n * LDK + k] = __float2bfloat16_rn(0.f);
            g_B2hi[n * LDK + k] = __float2bfloat16_rn(0.f);
            g_B2lo[n * LDK + k] = __float2bfloat16_rn(0.f);
        }
        return;
    }
    int e0 = ((b - WBLK) * blockDim.x + threadIdx.x) * 4;
    if (e0 >= N_EDGES) return;   // N_EDGES % 4 == 0
    int idx64 = ((ei32[1] | ei32[3] | ei32[5] | ei32[7]) == 0);
    int s0, s1, s2, s3;
    if (idx64) {
        const int4* p = (const int4*)(ei32 + 2 * (N_EDGES + e0));
        int4 a = p[0], c = p[1];
        s0 = a.x; s1 = a.z; s2 = c.x; s3 = c.z;   // low words of 4 int64
    } else {
        int4 a = *(const int4*)(ei32 + N_EDGES + e0);
        s0 = a.x; s1 = a.y; s2 = a.z; s3 = a.w;
    }
    const float4* q = (const float4*)(ea + (size_t)e0 * 3);
    float4 q0 = q[0], q1 = q[1], q2 = q[2];
    red_v4(&g_agg[s0], q0.x, q0.y, q0.z, 1.0f);
    red_v4(&g_agg[s1], q0.w, q1.x, q1.y, 1.0f);
    red_v4(&g_agg[s2], q1.z, q1.w, q2.x, 1.0f);
    red_v4(&g_agg[s3], q2.y, q2.z, q2.w, 1.0f);
}

// ---------------------------------------------------------------------------
// fused (persistent, 512 thr): four decoupled 32-row group pipelines per CTA;
// ldmatrix.x4 fragment loads (8 LDSM per k-step instead of 32 LDS.32).
// ---------------------------------------------------------------------------
__global__ __launch_bounds__(THREADS, 1)
void fused_kernel(const float* __restrict__ x,
                  const float* __restrict__ W1,
                  const float* __restrict__ b1g,
                  const float* __restrict__ W2,
                  const float* __restrict__ b2g,
                  float* __restrict__ out) {
    extern __shared__ char smem[];
    __nv_bfloat16* sAhi  = (__nv_bfloat16*)(smem + OFF_AHI);
    __nv_bfloat16* sAlo  = (__nv_bfloat16*)(smem + OFF_ALO);
    float* sMea = (float*)(smem + OFF_MEA);
    float* sW1c = (float*)(smem + OFF_W1C);
    float* sB1  = (float*)(smem + OFF_B1);
    float* sB2  = (float*)(smem + OFF_B2);
    unsigned* sZb = (unsigned*)(smem + OFF_ZB);
    float* sFix = (float*)(smem + OFF_FIX);

    const int tid = threadIdx.x, wid = tid >> 5, lane = tid & 31;
    const int gID = lane >> 2, tIG = lane & 3;
    const int grp = wid & 3;            // row group 0..3
    const int gtid = (wid >> 2) * 32 + lane;   // 0..127 within group
    const int barid = 1 + grp;
    const int wr = grp * 32;            // warp row base
    const int wc = (wid >> 2) * 32;     // warp col base

    const uint32_t smemU = smem_u32(smem);
    // per-lane ldmatrix offsets (bytes)
    const uint32_t aOff = (uint32_t)(((wr + (lane & 15)) * LDK + ((lane >> 4) << 3)) * 2);
    const uint32_t bOff = (uint32_t)(((wc + (lane & 7) + ((lane >> 4) << 3)) * LDK
                                      + (((lane >> 3) & 1) << 3)) * 2);

    // ---- one-time: biases, W1c, all 4 weight images ----
    if (tid < 128) { sB1[tid] = b1g[tid]; sB2[tid] = b2g[tid]; }
    for (int i = tid; i < 3 * 128; i += THREADS) sW1c[i] = W1[256 * 128 + i];
    {
        const uint4* s1 = (const uint4*)g_B1hi;
        const uint4* s2 = (const uint4*)g_B1lo;
        const uint4* s3 = (const uint4*)g_B2hi;
        const uint4* s4 = (const uint4*)g_B2lo;
        uint4* d1 = (uint4*)(smem + OFF_B1HI);
        uint4* d2 = (uint4*)(smem + OFF_B1LO);
        uint4* d3 = (uint4*)(smem + OFF_B2HI);
        uint4* d4 = (uint4*)(smem + OFF_B2LO);
        for (int i = tid; i < 128 * LDK * 2 / 16; i += THREADS) {
            d1[i] = s1[i]; d2[i] = s2[i]; d3[i] = s3[i]; d4[i] = s4[i];
        }
    }
    __syncthreads();

// ldmatrix-based layer: OFFBH/OFFBL are byte offsets of the B hi/lo images.
// Fragment<->register mapping is bit-identical to the previous scalar loads.
#define MMA_LAYER(OFFBH, OFFBL)                                                 \
    {                                                                           \
        uint32_t a0h = smemU + OFF_AHI + aOff;                                  \
        uint32_t a1h = a0h + 16 * LDK * 2;                                      \
        uint32_t a0l = smemU + OFF_ALO + aOff;                                  \
        uint32_t a1l = a0l + 16 * LDK * 2;                                      \
        uint32_t b0h = smemU + (OFFBH) + bOff;                                  \
        uint32_t b1h = b0h + 16 * LDK * 2;                                      \
        uint32_t b0l = smemU + (OFFBL) + bOff;                                  \
        uint32_t b1l = b0l + 16 * LDK * 2;                                      \
        _Pragma("unroll")                                                       \
        for (int ks = 0; ks < 8; ks++) {                                        \
            uint32_t aH[2][4], aL[2][4], bH[2][4], bL[2][4];                    \
            LDSM4(aH[0], a0h); LDSM4(aH[1], a1h);                               \
            LDSM4(bH[0], b0h); LDSM4(bH[1], b1h);                               \
            LDSM4(aL[0], a0l); LDSM4(aL[1], a1l);                               \
            LDSM4(bL[0], b0l); LDSM4(bL[1], b1l);                               \
            _Pragma("unroll")                                                   \
            for (int ma = 0; ma < 2; ma++)                                      \
                _Pragma("unroll")                                               \
                for (int na = 0; na < 4; na++) {                                \
                    const uint32_t* bhp = &bH[na >> 1][(na & 1) * 2];           \
                    const uint32_t* blp = &bL[na >> 1][(na & 1) * 2];           \
                    mma_bf16(acc[ma][na], aH[ma], bhp);                         \
                    mma_bf16(acc[ma][na], aL[ma], bhp);                         \
                    mma_bf16(acc[ma][na], aH[ma], blp);                         \
                }                                                               \
            a0h += 32; a1h += 32; a0l += 32; a1l += 32;                         \
            b0h += 32; b1h += 32; b0l += 32; b1l += 32;                         \
        }                                                                       \
    }

    for (int t = blockIdx.x; t < NBLK; t += gridDim.x) {
        const int node0 = t * TM;
        // protect own group's sA (prev MMA2 reads) + sZb/sMea before rewrite
        bar_grp(barid);

        // ---- mea + zero-degree ballot + consume-and-clear (warp g = group g rows) ----
        if (wid < 4) {
            int g = node0 + wid * 32 + lane;
            float4 a = make_float4(0.f, 0.f, 0.f, 1.f);
            if (g < N_NODES) {
                a = g_agg[g];
                g_agg[g] = make_float4(0.f, 0.f, 0.f, 0.f);   // restore invariant
            }
            unsigned zb = __ballot_sync(0xffffffffu, (g < N_NODES) && (a.w == 0.f));
            if (lane == 0) sZb[wid] = zb;
            float inv = 1.0f / fmaxf(a.w, 1.0f);
            int rr = wid * 32 + lane;
            sMea[rr * 4 + 0] = a.x * inv;
            sMea[rr * 4 + 1] = a.y * inv;
            sMea[rr * 4 + 2] = a.z * inv;
        }

        // ---- x -> sA hi/lo (own 32 rows only) ----
        const float4* x4 = (const float4*)x;
        for (int idx = gtid; idx < 32 * 32; idx += 128) {
            int rl = idx >> 5, kq = idx & 31;
            int r = wr + rl, g = node0 + r;
            float4 v = make_float4(0.f, 0.f, 0.f, 0.f);
            if (g < N_NODES) v = x4[(size_t)g * 32 + kq];
            int o = r * LDK + kq * 4;
            *(uint32_t*)(sAhi + o)     = pack_bf(v.x, v.y);
            *(uint32_t*)(sAhi + o + 2) = pack_bf(v.z, v.w);
            *(uint32_t*)(sAlo + o)     = pack_bf(bf_resid(v.x), bf_resid(v.y));
            *(uint32_t*)(sAlo + o + 2) = pack_bf(bf_resid(v.z), bf_resid(v.w));
        }
        bar_grp(barid);

        float acc[2][4][4];
#pragma unroll
        for (int ma = 0; ma < 2; ma++)
#pragma unroll
            for (int na = 0; na < 4; na++)
#pragma unroll
                for (int c = 0; c < 4; c++) acc[ma][na][c] = 0.f;

        MMA_LAYER(OFF_B1HI, OFF_B1LO)
        bar_grp(barid);   // group's A reads done before epilogue1 overwrites

        // ---- epilogue1: h = relu(acc + b1 + mea@W1c) -> sA hi/lo; reset acc ----
#pragma unroll
        for (int ma = 0; ma < 2; ma++) {
            int r0 = wr + ma * 16 + gID;
            float m00 = sMea[r0 * 4], m01 = sMea[r0 * 4 + 1], m02 = sMea[r0 * 4 + 2];
            int r1 = r0 + 8;
            float m10 = sMea[r1 * 4], m11 = sMea[r1 * 4 + 1], m12 = sMea[r1 * 4 + 2];
#pragma unroll
            for (int na = 0; na < 4; na++) {
                int c0 = wc + na * 8 + tIG * 2;
                float e0 = sB1[c0]     + m00 * sW1c[c0]     + m01 * sW1c[128 + c0]     + m02 * sW1c[256 + c0];
                float e1 = sB1[c0 + 1] + m00 * sW1c[c0 + 1] + m01 * sW1c[128 + c0 + 1] + m02 * sW1c[256 + c0 + 1];
                float f0 = sB1[c0]     + m10 * sW1c[c0]     + m11 * sW1c[128 + c0]     + m12 * sW1c[256 + c0];
                float f1 = sB1[c0 + 1] + m10 * sW1c[c0 + 1] + m11 * sW1c[128 + c0 + 1] + m12 * sW1c[256 + c0 + 1];
                float v0 = fmaxf(acc[ma][na][0] + e0, 0.f);
                float v1 = fmaxf(acc[ma][na][1] + e1, 0.f);
                float v2 = fmaxf(acc[ma][na][2] + f0, 0.f);
                float v3 = fmaxf(acc[ma][na][3] + f1, 0.f);
                *(uint32_t*)(sAhi + r0 * LDK + c0) = pack_bf(v0, v1);
                *(uint32_t*)(sAlo + r0 * LDK + c0) = pack_bf(bf_resid(v0), bf_resid(v1));
                *(uint32_t*)(sAhi + r1 * LDK + c0) = pack_bf(v2, v3);
                *(uint32_t*)(sAlo + r1 * LDK + c0) = pack_bf(bf_resid(v2), bf_resid(v3));
#pragma unroll
                for (int c = 0; c < 4; c++) acc[ma][na][c] = 0.f;
            }
        }
        bar_grp(barid);

        MMA_LAYER(OFF_B2HI, OFF_B2LO)

        // ---- epilogue2: out = acc + b2 (direct global stores, 8B each) ----
#pragma unroll
        for (int ma = 0; ma < 2; ma++) {
            int r0 = wr + ma * 16 + gID;
            int g0 = node0 + r0, g1 = g0 + 8;
#pragma unroll
            for (int na = 0; na < 4; na++) {
                int c0 = wc + na * 8 + tIG * 2;
                if (g0 < N_NODES) {
                    float2 v = make_float2(acc[ma][na][0] + sB2[c0], acc[ma][na][1] + sB2[c0 + 1]);
                    *(float2*)(out + (size_t)g0 * 128 + c0) = v;
                }
                if (g1 < N_NODES) {
                    float2 v = make_float2(acc[ma][na][2] + sB2[c0], acc[ma][na][3] + sB2[c0 + 1]);
                    *(float2*)(out + (size_t)g1 * 128 + c0) = v;
                }
            }
        }

        // ---- group-local fixup: exact fp32 recompute for zero-degree nodes ----
        {
            unsigned m = sZb[grp];   // written by warp grp this tile (ordered by bars)
            if (m) {
                float* fx = sFix + grp * 128;
                while (m) {
                    int b = __ffs(m) - 1;
                    m &= m - 1;
                    int n = node0 + wr + b;
                    float a1 = sB1[gtid];
                    for (int k = 0; k < 128; k++)
                        a1 = fmaf(x[(size_t)n * 128 + k], W1[k * 128 + gtid], a1);
                    fx[gtid] = fmaxf(a1, 0.f);
                    bar_grp(barid);
                    float a2 = sB2[gtid];
                    for (int k = 0; k < 128; k++)
                        a2 = fmaf(fx[k], W2[k * 128 + gtid], a2);
                    out[(size_t)n * 128 + gtid] = a2;
                    bar_grp(barid);
                }
            }
        }
    }
#undef MMA_LAYER
}

// ---------------------------------------------------------------------------
extern "C" void kernel_launch(void* const* d_in, const int* in_sizes, int n_in,
                              void* d_out, int out_size) {
    const float* x    = (const float*)d_in[0];
    const int*   ei32 = (const int*)d_in[1];
    const float* ea   = (const float*)d_in[2];
    const float* W1   = (const float*)d_in[5];
    const float* b1   = (const float*)d_in[6];
    const float* W2   = (const float*)d_in[7];
    const float* b2   = (const float*)d_in[8];
    float* out = (float*)d_out;

    cudaFuncSetAttribute(fused_kernel, cudaFuncAttributeMaxDynamicSharedMemorySize, SMEM_TOTAL);

    int eblk = (N_EDGES / 4 + 255) / 256;
    prep_scatter_kernel<<<WBLK + eblk, 256>>>(ei32, ea, W1, W2);
    fused_kernel<<<NPERS, THREADS, SMEM_TOTAL>>>(x, W1, b1, W2, b2, out);
}

// round 15
// speedup vs baseline: 1.1159x; 1.1159x over previous
#include <cuda_runtime.h>
#include <cuda_bf16.h>
#include <cstdint>

#define N_NODES 100000
#define N_EDGES 1600000
#define THREADS 384
#define NG 3          // groups per CTA (4 warps each)
#define NPERS 148     // persistent CTAs (~1 per SM)
#define NT32 3125     // 32-row tiles (100000 = 3125*32 exactly)
#define LDK 136       // padded K stride (272B rows -> conflict-free ldmatrix)
#define WBLK 64       // weight-image blocks inside prep_scatter
#define MROW (16 * LDK * 2)   // 16-row byte stride for ldmatrix pairs

// ---- SMEM byte offsets ----
#define OFF_B1HI 0            // 34816 each  [128][136] bf16
#define OFF_B1LO 34816
#define OFF_B2HI 69632
#define OFF_B2LO 104448
#define OFF_A    139264       // 3 groups x (hi 8704 + lo 8704) = 52224
#define AG_STRIDE 17408
#define OFF_MEA  191488       // 3 x [32][4] fp32 = 1536
#define OFF_W1C  193024       // [3][128] fp32 = 1536
#define OFF_B1   194560       // [128] fp32
#define OFF_B2   195072       // [128] fp32
#define OFF_ZB   195584       // [3] uint32 (+pad)
#define OFF_FIX  195616       // 3 x [128] fp32 = 1536
#define SMEM_TOTAL 197152

// ---- global scratch ----
// g_agg invariant: all-zero at launch start (static init first run; fused
// consume-and-clear restores it every execution / graph replay).
__device__ float4 g_agg[N_NODES];                      // sum_ea0..2, count
__device__ __align__(16) __nv_bfloat16 g_B1hi[128 * LDK];  // [n][k] = Wsum[k][n]
__device__ __align__(16) __nv_bfloat16 g_B1lo[128 * LDK];
__device__ __align__(16) __nv_bfloat16 g_B2hi[128 * LDK];  // [n][k] = W2[k][n]
__device__ __align__(16) __nv_bfloat16 g_B2lo[128 * LDK];

__device__ __forceinline__ uint32_t pack_bf(float a, float b) {
    __nv_bfloat162 t = __floats2bfloat162_rn(a, b);
    return *(uint32_t*)&t;
}
__device__ __forceinline__ float bf_resid(float v) {
    return v - __bfloat162float(__float2bfloat16_rn(v));
}
__device__ __forceinline__ void mma_bf16(float* c, const uint32_t* a, const uint32_t* b) {
    asm volatile(
        "mma.sync.aligned.m16n8k16.row.col.f32.bf16.bf16.f32 "
        "{%0,%1,%2,%3}, {%4,%5,%6,%7}, {%8,%9}, {%0,%1,%2,%3};"
        : "+f"(c[0]), "+f"(c[1]), "+f"(c[2]), "+f"(c[3])
        : "r"(a[0]), "r"(a[1]), "r"(a[2]), "r"(a[3]), "r"(b[0]), "r"(b[1]));
}
__device__ __forceinline__ void red_v4(float4* p, float a, float b, float c, float d) {
    asm volatile("red.global.add.v4.f32 [%0], {%1, %2, %3, %4};"
                 :: "l"(p), "f"(a), "f"(b), "f"(c), "f"(d) : "memory");
}
__device__ __forceinline__ void bar_grp(int id) {
    asm volatile("bar.sync %0, %1;" :: "r"(id), "r"(128) : "memory");
}
__device__ __forceinline__ uint32_t smem_u32(const void* p) {
    uint32_t a;
    asm("{ .reg .u64 t; cvta.to.shared.u64 t, %1; cvt.u32.u64 %0, t; }" : "=r"(a) : "l"(p));
    return a;
}
#define LDSM4(r, addr)                                                           \
    asm volatile("ldmatrix.sync.aligned.m8n8.x4.shared.b16 {%0,%1,%2,%3}, [%4];" \
        : "=r"((r)[0]), "=r"((r)[1]), "=r"((r)[2]), "=r"((r)[3]) : "r"(addr))

// ---------------------------------------------------------------------------
// prep_scatter: blocks [0,WBLK) build weight images; the rest scatter edges
// ---------------------------------------------------------------------------
__global__ void prep_scatter_kernel(const int* __restrict__ ei32,
                                    const float* __restrict__ ea,
                                    const float* __restrict__ W1,
                                    const float* __restrict__ W2) {
    int b = blockIdx.x;
    if (b < WBLK) {
        int tid = b * blockDim.x + threadIdx.x;
        int stride = WBLK * blockDim.x;
        for (int i = tid; i < 128 * 128; i += stride) {
            int n = i >> 7, k = i & 127;
            float v = W1[k * 128 + n] + W1[(128 + k) * 128 + n];   // Wsum^T
            __nv_bfloat16 h = __float2bfloat16_rn(v);
            g_B1hi[n * LDK + k] = h;
            g_B1lo[n * LDK + k] = __float2bfloat16_rn(v - __bfloat162float(h));
            float w = W2[k * 128 + n];                              // W2^T
            __nv_bfloat16 h2 = __float2bfloat16_rn(w);
            g_B2hi[n * LDK + k] = h2;
            g_B2lo[n * LDK + k] = __float2bfloat16_rn(w - __bfloat162float(h2));
        }
        for (int i = tid; i < 128 * (LDK - 128); i += stride) {
            int n = i / (LDK - 128), k = 128 + i % (LDK - 128);
            g_B1hi[n * LDK + k] = __float2bfloat16_rn(0.f);
            g_B1lo[n * LDK + k] = __float2bfloat16_rn(0.f);
            g_B2hi[n * LDK + k] = __float2bfloat16_rn(0.f);
            g_B2lo[n * LDK + k] = __float2bfloat16_rn(0.f);
        }
        return;
    }
    int e0 = ((b - WBLK) * blockDim.x + threadIdx.x) * 4;
    if (e0 >= N_EDGES) return;   // N_EDGES % 4 == 0
    int idx64 = ((ei32[1] | ei32[3] | ei32[5] | ei32[7]) == 0);
    int s0, s1, s2, s3;
    if (idx64) {
        const int4* p = (const int4*)(ei32 + 2 * (N_EDGES + e0));
        int4 a = p[0], c = p[1];
        s0 = a.x; s1 = a.z; s2 = c.x; s3 = c.z;   // low words of 4 int64
    } else {
        int4 a = *(const int4*)(ei32 + N_EDGES + e0);
        s0 = a.x; s1 = a.y; s2 = a.z; s3 = a.w;
    }
    const float4* q = (const float4*)(ea + (size_t)e0 * 3);
    float4 q0 = q[0], q1 = q[1], q2 = q[2];
    red_v4(&g_agg[s0], q0.x, q0.y, q0.z, 1.0f);
    red_v4(&g_agg[s1], q0.w, q1.x, q1.y, 1.0f);
    red_v4(&g_agg[s2], q1.z, q1.w, q2.x, 1.0f);
    red_v4(&g_agg[s3], q2.y, q2.z, q2.w, 1.0f);
}

// ---------------------------------------------------------------------------
// fused (persistent, 384 thr): 3 independent 32-row group pipelines per CTA,
// register-prefetched x + g_agg, double-buffered ldmatrix fragments.
// ---------------------------------------------------------------------------
__global__ __launch_bounds__(THREADS, 1)
void fused_kernel(const float* __restrict__ x,
                  const float* __restrict__ W1,
                  const float* __restrict__ b1g,
                  const float* __restrict__ W2,
                  const float* __restrict__ b2g,
                  float* __restrict__ out) {
    extern __shared__ char smem[];
    float* sW1c = (float*)(smem + OFF_W1C);
    float* sB1  = (float*)(smem + OFF_B1);
    float* sB2  = (float*)(smem + OFF_B2);
    unsigned* sZb = (unsigned*)(smem + OFF_ZB);

    const int tid = threadIdx.x, wid = tid >> 5, lane = tid & 31;
    const int gID = lane >> 2, tIG = lane & 3;
    const int grp = wid >> 2;           // group 0..2
    const int w4 = wid & 3;             // warp within group
    const int gtid = w4 * 32 + lane;    // 0..127 within group
    const int barid = 1 + grp;
    const int wc = w4 * 32;             // warp col base

    __nv_bfloat16* sAhi = (__nv_bfloat16*)(smem + OFF_A + grp * AG_STRIDE);
    __nv_bfloat16* sAlo = (__nv_bfloat16*)(smem + OFF_A + grp * AG_STRIDE + 8704);
    float* sMeaG = (float*)(smem + OFF_MEA) + grp * 128;   // [32][4]
    float* sFixG = (float*)(smem + OFF_FIX) + grp * 128;

    const uint32_t smemU = smem_u32(smem);
    const uint32_t aBaseH = smemU + OFF_A + grp * AG_STRIDE
                          + (uint32_t)(((lane & 15) * LDK + ((lane >> 4) << 3)) * 2);
    const uint32_t aBaseL = aBaseH + 8704;
    const uint32_t bOff = (uint32_t)(((wc + (lane & 7) + ((lane >> 4) << 3)) * LDK
                                      + (((lane >> 3) & 1) << 3)) * 2);

    // ---- one-time: biases, W1c, all 4 weight images ----
    if (tid < 128) { sB1[tid] = b1g[tid]; sB2[tid] = b2g[tid]; }
    for (int i = tid; i < 3 * 128; i += THREADS) sW1c[i] = W1[256 * 128 + i];
    {
        const uint4* s1 = (const uint4*)g_B1hi;
        const uint4* s2 = (const uint4*)g_B1lo;
        const uint4* s3 = (const uint4*)g_B2hi;
        const uint4* s4 = (const uint4*)g_B2lo;
        uint4* d1 = (uint4*)(smem + OFF_B1HI);
        uint4* d2 = (uint4*)(smem + OFF_B1LO);
        uint4* d3 = (uint4*)(smem + OFF_B2HI);
        uint4* d4 = (uint4*)(smem + OFF_B2LO);
        for (int i = tid; i < 128 * LDK * 2 / 16; i += THREADS) {
            d1[i] = s1[i]; d2[i] = s2[i]; d3[i] = s3[i]; d4[i] = s4[i];
        }
    }
    __syncthreads();

// double-buffered ldmatrix layer; fragment<->reg mapping identical to R13.
#define MMA_LAYER(OFFBH, OFFBL)                                                 \
    {                                                                           \
        uint32_t pah = aBaseH, pal = aBaseL;                                    \
        uint32_t pbh = smemU + (OFFBH) + bOff;                                  \
        uint32_t pbl = smemU + (OFFBL) + bOff;                                  \
        uint32_t aH[2][2][4], aL[2][2][4], bH[2][2][4], bL[2][2][4];            \
        LDSM4(aH[0][0], pah); LDSM4(aH[0][1], pah + MROW);                      \
        LDSM4(bH[0][0], pbh); LDSM4(bH[0][1], pbh + MROW);                      \
        LDSM4(aL[0][0], pal); LDSM4(aL[0][1], pal + MROW);                      \
        LDSM4(bL[0][0], pbl); LDSM4(bL[0][1], pbl + MROW);                      \
        _Pragma("unroll")                                                       \
        for (int ks = 0; ks < 8; ks++) {                                        \
            const int cur = ks & 1, nxt = cur ^ 1;                              \
            if (ks < 7) {                                                       \
                pah += 32; pal += 32; pbh += 32; pbl += 32;                     \
                LDSM4(aH[nxt][0], pah); LDSM4(aH[nxt][1], pah + MROW);          \
                LDSM4(bH[nxt][0], pbh); LDSM4(bH[nxt][1], pbh + MROW);          \
                LDSM4(aL[nxt][0], pal); LDSM4(aL[nxt][1], pal + MROW);          \
                LDSM4(bL[nxt][0], pbl); LDSM4(bL[nxt][1], pbl + MROW);          \
            }                                                                   \
            _Pragma("unroll")                                                   \
            for (int ma = 0; ma < 2; ma++)                                      \
                _Pragma("unroll")                                               \
                for (int na = 0; na < 4; na++) {                                \
                    const uint32_t* bhp = &bH[cur][na >> 1][(na & 1) * 2];      \
                    const uint32_t* blp = &bL[cur][na >> 1][(na & 1) * 2];      \
                    mma_bf16(acc[ma][na], aH[cur][ma], bhp);                    \
                    mma_bf16(acc[ma][na], aL[cur][ma], bhp);                    \
                    mma_bf16(acc[ma][na], aH[cur][ma], blp);                    \
                }                                                               \
        }                                                                       \
    }

    const int stride = gridDim.x * NG;
    int t = blockIdx.x * NG + grp;
    const float4* x4 = (const float4*)x;

    // ---- prologue prefetch (tile t) ----
    float4 px[8];
    float4 pmea = make_float4(0.f, 0.f, 0.f, 1.f);
    if (t < NT32) {
#pragma unroll
        for (int i = 0; i < 8; i++) {
            int idx = i * 128 + gtid, r = idx >> 5, kq = idx & 31;
            px[i] = x4[((size_t)t * 32 + r) * 32 + kq];
        }
        if (w4 == 0) {
            int g = t * 32 + lane;
            pmea = g_agg[g];
            g_agg[g] = make_float4(0.f, 0.f, 0.f, 0.f);   // restore invariant
        }
    }

    for (; t < NT32; ) {
        bar_grp(barid);   // own sA / sMea / sZb safe to overwrite

        // ---- mea + zero-degree ballot (from prefetched pmea) ----
        if (w4 == 0) {
            unsigned zb = __ballot_sync(0xffffffffu, pmea.w == 0.f);
            if (lane == 0) sZb[grp] = zb;
            float inv = 1.0f / fmaxf(pmea.w, 1.0f);
            sMeaG[lane * 4 + 0] = pmea.x * inv;
            sMeaG[lane * 4 + 1] = pmea.y * inv;
            sMeaG[lane * 4 + 2] = pmea.z * inv;
        }

        // ---- prefetched x -> sA hi/lo ----
#pragma unroll
        for (int i = 0; i < 8; i++) {
            int idx = i * 128 + gtid, r = idx >> 5, kq = idx & 31;
            int o = r * LDK + kq * 4;
            float4 v = px[i];
            *(uint32_t*)(sAhi + o)     = pack_bf(v.x, v.y);
            *(uint32_t*)(sAhi + o + 2) = pack_bf(v.z, v.w);
            *(uint32_t*)(sAlo + o)     = pack_bf(bf_resid(v.x), bf_resid(v.y));
            *(uint32_t*)(sAlo + o + 2) = pack_bf(bf_resid(v.z), bf_resid(v.w));
        }

        // ---- prefetch next tile (in flight through both MMA phases) ----
        const int tn = t + stride;
        if (tn < NT32) {
#pragma unroll
            for (int i = 0; i < 8; i++) {
                int idx = i * 128 + gtid, r = idx >> 5, kq = idx & 31;
                px[i] = x4[((size_t)tn * 32 + r) * 32 + kq];
            }
            if (w4 == 0) {
                int g = tn * 32 + lane;
                pmea = g_agg[g];
                g_agg[g] = make_float4(0.f, 0.f, 0.f, 0.f);
            }
        }
        bar_grp(barid);

        float acc[2][4][4];
#pragma unroll
        for (int ma = 0; ma < 2; ma++)
#pragma unroll
            for (int na = 0; na < 4; na++)
#pragma unroll
                for (int c = 0; c < 4; c++) acc[ma][na][c] = 0.f;

        MMA_LAYER(OFF_B1HI, OFF_B1LO)
        bar_grp(barid);   // group's A reads done before epilogue1 overwrites

        // ---- epilogue1: h = relu(acc + b1 + mea@W1c) -> sA hi/lo; reset acc ----
#pragma unroll
        for (int ma = 0; ma < 2; ma++) {
            int r0 = ma * 16 + gID;
            float m00 = sMeaG[r0 * 4], m01 = sMeaG[r0 * 4 + 1], m02 = sMeaG[r0 * 4 + 2];
            int r1 = r0 + 8;
            float m10 = sMeaG[r1 * 4], m11 = sMeaG[r1 * 4 + 1], m12 = sMeaG[r1 * 4 + 2];
#pragma unroll
            for (int na = 0; na < 4; na++) {
                int c0 = wc + na * 8 + tIG * 2;
                float e0 = sB1[c0]     + m00 * sW1c[c0]     + m01 * sW1c[128 + c0]     + m02 * sW1c[256 + c0];
                float e1 = sB1[c0 + 1] + m00 * sW1c[c0 + 1] + m01 * sW1c[128 + c0 + 1] + m02 * sW1c[256 + c0 + 1];
                float f0 = sB1[c0]     + m10 * sW1c[c0]     + m11 * sW1c[128 + c0]     + m12 * sW1c[256 + c0];
                float f1 = sB1[c0 + 1] + m10 * sW1c[c0 + 1] + m11 * sW1c[128 + c0 + 1] + m12 * sW1c[256 + c0 + 1];
                float v0 = fmaxf(acc[ma][na][0] + e0, 0.f);
                float v1 = fmaxf(acc[ma][na][1] + e1, 0.f);
                float v2 = fmaxf(acc[ma][na][2] + f0, 0.f);
                float v3 = fmaxf(acc[ma][na][3] + f1, 0.f);
                *(uint32_t*)(sAhi + r0 * LDK + c0) = pack_bf(v0, v1);
                *(uint32_t*)(sAlo + r0 * LDK + c0) = pack_bf(bf_resid(v0), bf_resid(v1));
                *(uint32_t*)(sAhi + r1 * LDK + c0) = pack_bf(v2, v3);
                *(uint32_t*)(sAlo + r1 * LDK + c0) = pack_bf(bf_resid(v2), bf_resid(v3));
#pragma unroll
                for (int c = 0; c < 4; c++) acc[ma][na][c] = 0.f;
            }
        }
        bar_grp(barid);

        MMA_LAYER(OFF_B2HI, OFF_B2LO)

        // ---- epilogue2: out = acc + b2 (rows always in-bounds: 3125*32 = N) ----
#pragma unroll
        for (int ma = 0; ma < 2; ma++) {
            int r0 = ma * 16 + gID;
            size_t g0 = (size_t)t * 32 + r0;
#pragma unroll
            for (int na = 0; na < 4; na++) {
                int c0 = wc + na * 8 + tIG * 2;
                float2 v0 = make_float2(acc[ma][na][0] + sB2[c0], acc[ma][na][1] + sB2[c0 + 1]);
                *(float2*)(out + g0 * 128 + c0) = v0;
                float2 v1 = make_float2(acc[ma][na][2] + sB2[c0], acc[ma][na][3] + sB2[c0 + 1]);
                *(float2*)(out + (g0 + 8) * 128 + c0) = v1;
            }
        }

        // ---- group-local fixup: exact fp32 recompute for zero-degree nodes ----
        {
            unsigned m = sZb[grp];
            if (m) {
                while (m) {
                    int b = __ffs(m) - 1;
                    m &= m - 1;
                    size_t n = (size_t)t * 32 + b;
                    float a1 = sB1[gtid];
                    for (int k = 0; k < 128; k++)
                        a1 = fmaf(x[n * 128 + k], W1[k * 128 + gtid], a1);
                    sFixG[gtid] = fmaxf(a1, 0.f);
                    bar_grp(barid);
                    float a2 = sB2[gtid];
                    for (int k = 0; k < 128; k++)
                        a2 = fmaf(sFixG[k], W2[k * 128 + gtid], a2);
                    out[n * 128 + gtid] = a2;
                    bar_grp(barid);
                }
            }
        }
        t = tn;
    }
#undef MMA_LAYER
}

// ---------------------------------------------------------------------------
extern "C" void kernel_launch(void* const* d_in, const int* in_sizes, int n_in,
                              void* d_out, int out_size) {
    const float* x    = (const float*)d_in[0];
    const int*   ei32 = (const int*)d_in[1];
    const float* ea   = (const float*)d_in[2];
    const float* W1   = (const float*)d_in[5];
    const float* b1   = (const float*)d_in[6];
    const float* W2   = (const float*)d_in[7];
    const float* b2   = (const float*)d_in[8];
    float* out = (float*)d_out;

    cudaFuncSetAttribute(fused_kernel, cudaFuncAttributeMaxDynamicSharedMemorySize, SMEM_TOTAL);

    int eblk = (N_EDGES / 4 + 255) / 256;
    prep_scatter_kernel<<<WBLK + eblk, 256>>>(ei32, ea, W1, W2);
    fused_kernel<<<NPERS, THREADS, SMEM_TOTAL>>>(x, W1, b1, W2, b2, out);
}